// round 8
// baseline (speedup 1.0000x reference)
#include <cuda_runtime.h>
#include <math.h>

// Problem constants
#define G2   64
#define Hh   64
#define Aa   1024
#define Ss   32
#define Nn   64
#define Pp   4096
#define Bb   2048   // Ss * Nn
#define KS   32     // k-splits for Wc

typedef unsigned long long ull;

// -------- packed f32x2 helpers --------
__device__ __forceinline__ ull pk2(float lo, float hi) {
    ull r; asm("mov.b64 %0, {%1,%2};" : "=l"(r) : "f"(lo), "f"(hi)); return r;
}
__device__ __forceinline__ void upk2(ull v, float& lo, float& hi) {
    asm("mov.b64 {%0,%1}, %2;" : "=f"(lo), "=f"(hi) : "l"(v));
}
__device__ __forceinline__ ull ffma2(ull a, ull b, ull c) {
    ull d; asm("fma.rn.f32x2 %0, %1, %2, %3;" : "=l"(d) : "l"(a), "l"(b), "l"(c));
    return d;
}

// -------- device scratch (no allocations allowed) --------
__device__ float g_occ[Bb * G2];          // occupancy counts (B,64)
__device__ float g_c[Bb * Aa];            // h@W_dec + b_dec + b_enc
__device__ float g_ctx[Bb];               // attention-pooled scalar context
__device__ float g_wcp[KS * 70 * Aa];     // k-split partials of [W_out;b_out]@W_mlp
__device__ float g_wc[70 * Aa];           // fused weight (69 rows) + bias row
__device__ float g_y[Bb * Aa];            // pre-norm activations
__device__ float g_part[256 * Aa];        // per-y-block column sum/sumsq partials
__device__ float g_scale[Aa];
__device__ float g_shift[Aa];

// ---------------------------------------------------------------------------
// 1) occupancy: 8 pedestrians per block, scene read once per block.
__global__ __launch_bounds__(256) void occ_kernel(const float* __restrict__ end_pos,
                                                  const float* __restrict__ scene) {
    int grp = blockIdx.x & 7;
    int s   = blockIdx.x >> 3;
    int pedbase = s * 64 + grp * 8;

    __shared__ int bins[8][G2];
    __shared__ float4 boxsh[8];
    for (int i = threadIdx.x; i < 8 * G2; i += 256) ((int*)bins)[i] = 0;
    if (threadIdx.x < 8) {
        float ex = end_pos[(pedbase + threadIdx.x) * 2 + 0];
        float ey = end_pos[(pedbase + threadIdx.x) * 2 + 1];
        boxsh[threadIdx.x] = make_float4(ex - 1.0f, ey + 1.0f, ex + 1.0f, ey - 1.0f);
    }
    __syncthreads();

    float4 bx[8];
#pragma unroll
    for (int j = 0; j < 8; j++) bx[j] = boxsh[j];

    const float2* sc = reinterpret_cast<const float2*>(scene) + (size_t)s * Pp;
    for (int p = threadIdx.x; p < Pp; p += 256) {
        float2 q = sc[p];
#pragma unroll
        for (int j = 0; j < 8; j++) {
            bool in = (q.x < bx[j].z) && (q.x > bx[j].x) &&
                      (q.y < bx[j].y) && (q.y > bx[j].w);
            if (in) {
                float cx = floorf(((q.x - bx[j].x) / 2.0f) * 8.0f);
                float cy = floorf(((bx[j].y - q.y) / 2.0f) * 8.0f);
                int cell = (int)(cx + cy * 8.0f);
                if (cell >= 0 && cell < G2) {
                    atomicAdd(&bins[j][cell], 1);
                } else {
                    long flat = (long)(pedbase + j) * G2 + cell;
                    if (flat >= 0 && flat < (long)Bb * G2)
                        atomicAdd(&g_occ[flat], 1.0f);   // rare bleed, exact int adds
                }
            }
        }
    }
    __syncthreads();
    for (int i = threadIdx.x; i < 8 * G2; i += 256) {
        int v = ((int*)bins)[i];
        if (v) atomicAdd(&g_occ[pedbase * G2 + i], (float)v);
    }
}

// ---------------------------------------------------------------------------
// 2) c[b,a] = sum_k h[b,k]*W_dec[k,a] + b_dec[a] + b_enc[a]
//    Also zeroes g_occ (runs before occ_kernel in stream order).
__global__ __launch_bounds__(128) void c_kernel(const float* __restrict__ h,
                                                const float* __restrict__ Wd,
                                                const float* __restrict__ bd,
                                                const float* __restrict__ be) {
    // fold-in: zero occupancy buffer (1024 blocks x 32 float4 = 128K floats)
    {
        int bid = blockIdx.y * gridDim.x + blockIdx.x;
        if (threadIdx.x < 32)
            reinterpret_cast<float4*>(g_occ)[bid * 32 + threadIdx.x] =
                make_float4(0.f, 0.f, 0.f, 0.f);
    }

    int a  = blockIdx.x * 128 + threadIdx.x;
    int b0 = blockIdx.y * 16;
    __shared__ __align__(16) float hp[Hh * 16];   // hp[k*16 + bl] = h[b0+bl][k]
    for (int idx = threadIdx.x; idx < 16 * Hh; idx += 128) {
        int bl = idx >> 6, k = idx & 63;
        hp[k * 16 + bl] = h[(b0 + bl) * Hh + k];
    }
    __syncthreads();

    ull acc[8] = {0, 0, 0, 0, 0, 0, 0, 0};
    const ulonglong2* hpu = reinterpret_cast<const ulonglong2*>(hp);
#pragma unroll 8
    for (int k = 0; k < Hh; k++) {
        float w = Wd[k * Aa + a];
        ull ww = pk2(w, w);
#pragma unroll
        for (int jj = 0; jj < 4; jj++) {
            ulonglong2 v = hpu[k * 4 + jj];
            acc[2 * jj]     = ffma2(v.x, ww, acc[2 * jj]);
            acc[2 * jj + 1] = ffma2(v.y, ww, acc[2 * jj + 1]);
        }
    }
    float bias = bd[a] + be[a];
#pragma unroll
    for (int j = 0; j < 8; j++) {
        float lo, hi; upk2(acc[j], lo, hi);
        g_c[(size_t)(b0 + 2 * j) * Aa + a]     = lo + bias;
        g_c[(size_t)(b0 + 2 * j + 1) * Aa + a] = hi + bias;
    }
}

// ---------------------------------------------------------------------------
// 3) fused e / softmax / ctx, packed over the a-dimension.
//    block 128 = 8 b-rows x 16 threads, 4 g per thread. grid: B/8 = 256.
__global__ __launch_bounds__(128) void ectx_kernel(const float* __restrict__ We,
                                                   const float* __restrict__ wf) {
    int b0  = blockIdx.x * 8;
    int tid = threadIdx.x;
    int bl  = tid >> 4;   // 0..7 local b
    int gq  = tid & 15;
    int b   = b0 + bl;

    __shared__ __align__(16) float we_s[128], wf_s[128];
    __shared__ __align__(16) float c_s[8][132];   // 132: conflict-free, 528B rows

    float og[4];
    ull ogw[4], e2[4];
#pragma unroll
    for (int i = 0; i < 4; i++) {
        og[i]  = g_occ[b * G2 + gq * 4 + i];
        ogw[i] = pk2(og[i], og[i]);
        e2[i]  = 0ull;
    }

    for (int a0 = 0; a0 < Aa; a0 += 128) {
        __syncthreads();
        we_s[tid] = We[a0 + tid];
        wf_s[tid] = wf[a0 + tid];
        for (int i = tid; i < 8 * 128; i += 128) {
            int bi = i >> 7, j = i & 127;
            c_s[bi][j] = g_c[(size_t)(b0 + bi) * Aa + a0 + j];
        }
        __syncthreads();
        const ull* weu = reinterpret_cast<const ull*>(we_s);
        const ull* wfu = reinterpret_cast<const ull*>(wf_s);
        const ull* cu  = reinterpret_cast<const ull*>(&c_s[bl][0]);
#pragma unroll 4
        for (int jj = 0; jj < 64; jj++) {
            ull we2 = weu[jj];
            ull wf2 = wfu[jj];
            ull c2  = cu[jj];
#pragma unroll
            for (int i = 0; i < 4; i++) {
                ull x2 = ffma2(ogw[i], we2, c2);
                float lo, hi; upk2(x2, lo, hi);
                lo = fmaxf(lo, 0.0f);
                hi = fmaxf(hi, 0.0f);
                e2[i] = ffma2(pk2(lo, hi), wf2, e2[i]);
            }
        }
    }

    float e[4];
#pragma unroll
    for (int i = 0; i < 4; i++) { float lo, hi; upk2(e2[i], lo, hi); e[i] = lo + hi; }

    // softmax over the 64 g spread across 16 lanes (width-16 shuffles)
    float m = fmaxf(fmaxf(e[0], e[1]), fmaxf(e[2], e[3]));
#pragma unroll
    for (int off = 8; off >= 1; off >>= 1)
        m = fmaxf(m, __shfl_xor_sync(0xffffffffu, m, off, 16));
    float s = 0.f, cx = 0.f;
#pragma unroll
    for (int i = 0; i < 4; i++) {
        float ex = __expf(e[i] - m);
        s += ex;
        cx = fmaf(ex, og[i], cx);
    }
#pragma unroll
    for (int off = 8; off >= 1; off >>= 1) {
        s  += __shfl_xor_sync(0xffffffffu, s, off, 16);
        cx += __shfl_xor_sync(0xffffffffu, cx, off, 16);
    }
    if (gq == 0) g_ctx[b] = cx / s;
}

// ---------------------------------------------------------------------------
// 4) Wc partials: rows 0..68 = W_out @ W_mlp, row 69 = b_out @ W_mlp.
//    grid (8 a-tiles, 4 r-splits of 18, 32 k-splits of 32), block 128.
//    1024 blocks -> ~28 warps/SM; Wm re-reads hit L2 (4 MB resident).
__global__ __launch_bounds__(128) void wc_kernel(const float* __restrict__ Wo,
                                                 const float* __restrict__ bo,
                                                 const float* __restrict__ Wm) {
    int a  = blockIdx.x * 128 + threadIdx.x;
    int r0 = blockIdx.y * 18;
    int k0 = blockIdx.z * 32;
    __shared__ __align__(16) float ws[9 * 32 * 2];   // pair-interleaved

    for (int idx = threadIdx.x; idx < 9 * 32; idx += 128) {
        int p = idx >> 5, k = idx & 31;
        int r = r0 + 2 * p;
        float v0 = 0.f, v1 = 0.f;
        if (r < 69)       v0 = Wo[r * Aa + k0 + k];
        else if (r == 69) v0 = bo[k0 + k];
        if (r + 1 < 69)       v1 = Wo[(r + 1) * Aa + k0 + k];
        else if (r + 1 == 69) v1 = bo[k0 + k];
        ws[idx * 2]     = v0;
        ws[idx * 2 + 1] = v1;
    }
    __syncthreads();

    ull acc[9];
#pragma unroll
    for (int p = 0; p < 9; p++) acc[p] = 0ull;

    const ulonglong2* wsu = reinterpret_cast<const ulonglong2*>(ws);
#pragma unroll 2
    for (int k = 0; k < 32; k += 2) {
        float w0 = Wm[(size_t)(k0 + k) * Aa + a];
        float w1 = Wm[(size_t)(k0 + k + 1) * Aa + a];
        ull ww0 = pk2(w0, w0), ww1 = pk2(w1, w1);
#pragma unroll
        for (int p = 0; p < 9; p++) {
            ulonglong2 v = wsu[p * 16 + (k >> 1)];   // pairs for k and k+1
            acc[p] = ffma2(v.x, ww0, acc[p]);
            acc[p] = ffma2(v.y, ww1, acc[p]);
        }
    }
    float* dst = g_wcp + (size_t)blockIdx.z * (70 * Aa);
#pragma unroll
    for (int p = 0; p < 9; p++) {
        int r = r0 + 2 * p;
        float lo, hi; upk2(acc[p], lo, hi);
        if (r < 70)     dst[r * Aa + a]       = lo;
        if (r + 1 < 70) dst[(r + 1) * Aa + a] = hi;
    }
}

__global__ void wcmerge_kernel() {
    int i = blockIdx.x * blockDim.x + threadIdx.x;   // over 70*1024/4
    if (i >= 70 * Aa / 4) return;
    float4 sum = make_float4(0.f, 0.f, 0.f, 0.f);
#pragma unroll
    for (int p = 0; p < KS; p++) {
        float4 v = reinterpret_cast<const float4*>(g_wcp + (size_t)p * 70 * Aa)[i];
        sum.x += v.x; sum.y += v.y; sum.z += v.z; sum.w += v.w;
    }
    reinterpret_cast<float4*>(g_wc)[i] = sum;
}

// ---------------------------------------------------------------------------
// 5) y[b,a] = sum_r u[b,r]*Wc[r,a] + bias; ALSO emits per-block column
//    sum/sumsq partials (fold-in of the old colreduce kernel).
__global__ __launch_bounds__(128) void y_kernel(const float* __restrict__ h,
                                                const float* __restrict__ ep,
                                                const float* __restrict__ rp,
                                                const float* __restrict__ bm) {
    int a  = blockIdx.x * 128 + threadIdx.x;
    int b0 = blockIdx.y * 16;
    __shared__ __align__(16) float us[69 * 16];   // us[r*16 + bl] = u[b0+bl][r]
    for (int idx = threadIdx.x; idx < 69 * 16; idx += 128) {
        int r = idx >> 4, bl = idx & 15;
        int b = b0 + bl;
        float v;
        if (r == 0)      v = g_ctx[b];
        else if (r < 65) v = h[b * Hh + (r - 1)];
        else if (r < 67) v = ep[b * 2 + (r - 65)];
        else             v = rp[b * 2 + (r - 67)];
        us[idx] = v;
    }
    __syncthreads();

    ull acc[8] = {0, 0, 0, 0, 0, 0, 0, 0};
    const ulonglong2* usu = reinterpret_cast<const ulonglong2*>(us);
#pragma unroll 4
    for (int r = 0; r < 69; r++) {
        float w = g_wc[r * Aa + a];
        ull ww = pk2(w, w);
#pragma unroll
        for (int jj = 0; jj < 4; jj++) {
            ulonglong2 v = usu[r * 4 + jj];
            acc[2 * jj]     = ffma2(v.x, ww, acc[2 * jj]);
            acc[2 * jj + 1] = ffma2(v.y, ww, acc[2 * jj + 1]);
        }
    }
    float bias = g_wc[69 * Aa + a] + bm[a];
    float s = 0.f, s2 = 0.f;
#pragma unroll
    for (int j = 0; j < 8; j++) {
        float lo, hi; upk2(acc[j], lo, hi);
        float v0 = lo + bias, v1 = hi + bias;
        g_y[(size_t)(b0 + 2 * j) * Aa + a]     = v0;
        g_y[(size_t)(b0 + 2 * j + 1) * Aa + a] = v1;
        s += v0 + v1;
        s2 = fmaf(v0, v0, s2);
        s2 = fmaf(v1, v1, s2);
    }
    g_part[(blockIdx.y * 2 + 0) * Aa + a] = s;
    g_part[(blockIdx.y * 2 + 1) * Aa + a] = s2;
}

// ---------------------------------------------------------------------------
// 6) combine 128 partials -> scale/shift for the batch-dim layernorm
__global__ __launch_bounds__(256) void stats_kernel(const float* __restrict__ gamma,
                                                    const float* __restrict__ beta) {
    int a = blockIdx.x * blockDim.x + threadIdx.x;
    if (a >= Aa) return;
    float s = 0.f, s2 = 0.f;
#pragma unroll 8
    for (int j = 0; j < 128; j++) {
        s  += g_part[(j * 2 + 0) * Aa + a];
        s2 += g_part[(j * 2 + 1) * Aa + a];
    }
    const float inv = 1.0f / (float)Bb;
    float mu  = s * inv;
    float var = s2 * inv - mu * mu;
    float r   = rsqrtf(var + 1e-5f);
    float sc  = gamma[a] * r;
    g_scale[a] = sc;
    g_shift[a] = beta[a] - mu * sc;
}

// 7) out = relu(y * scale + shift), vectorized
__global__ __launch_bounds__(256) void finalize_kernel(float* __restrict__ out) {
    int idx = blockIdx.x * blockDim.x + threadIdx.x;   // over B*A/4
    const int n = Bb * Aa / 4;
    if (idx >= n) return;
    float4 v = reinterpret_cast<const float4*>(g_y)[idx];
    int a = (idx * 4) & (Aa - 1);
    float4 sc = *reinterpret_cast<const float4*>(&g_scale[a]);
    float4 sh = *reinterpret_cast<const float4*>(&g_shift[a]);
    float4 o;
    o.x = fmaxf(fmaf(v.x, sc.x, sh.x), 0.f);
    o.y = fmaxf(fmaf(v.y, sc.y, sh.y), 0.f);
    o.z = fmaxf(fmaf(v.z, sc.z, sh.z), 0.f);
    o.w = fmaxf(fmaf(v.w, sc.w, sh.w), 0.f);
    reinterpret_cast<float4*>(out)[idx] = o;
}

// ---------------------------------------------------------------------------
extern "C" void kernel_launch(void* const* d_in, const int* in_sizes, int n_in,
                              void* d_out, int out_size) {
    const float* h_states = (const float*)d_in[0];   // (1,B,H)
    const float* end_pos  = (const float*)d_in[1];   // (B,2)
    const float* rel_pos  = (const float*)d_in[2];   // (B,2)
    const float* scene    = (const float*)d_in[3];   // (S,P,2)
    const float* W_enc    = (const float*)d_in[4];   // (1,A)
    const float* b_enc    = (const float*)d_in[5];   // (A)
    const float* W_dec    = (const float*)d_in[6];   // (H,A)
    const float* b_dec    = (const float*)d_in[7];   // (A)
    const float* w_full   = (const float*)d_in[8];   // (A,1)
    // d_in[9]  = b_full (softmax-shift invariant -> unused)
    const float* W_out    = (const float*)d_in[10];  // (69,A)
    const float* b_out    = (const float*)d_in[11];  // (A)
    const float* W_mlp    = (const float*)d_in[12];  // (A,A)
    const float* b_mlp    = (const float*)d_in[13];  // (A)
    const float* gamma    = (const float*)d_in[14];  // (A)
    const float* beta     = (const float*)d_in[15];  // (A)
    float* out = (float*)d_out;

    // c_kernel also zeroes g_occ; must precede occ_kernel (same stream).
    c_kernel<<<dim3(Aa / 128, Bb / 16), 128>>>(h_states, W_dec, b_dec, b_enc);
    occ_kernel<<<Ss * 8, 256>>>(end_pos, scene);
    wc_kernel<<<dim3(Aa / 128, 4, KS), 128>>>(W_out, b_out, W_mlp);
    wcmerge_kernel<<<(70 * Aa / 4 + 255) / 256, 256>>>();
    ectx_kernel<<<Bb / 8, 128>>>(W_enc, w_full);
    y_kernel<<<dim3(Aa / 128, Bb / 16), 128>>>(h_states, end_pos, rel_pos, b_mlp);
    stats_kernel<<<(Aa + 255) / 256, 256>>>(gamma, beta);
    finalize_kernel<<<(Bb * Aa / 4 + 255) / 256, 256>>>(out);
}

// round 9
// speedup vs baseline: 1.1734x; 1.1734x over previous
#include <cuda_runtime.h>
#include <math.h>

// Problem constants
#define G2   64
#define Hh   64
#define Aa   1024
#define Ss   32
#define Nn   64
#define Pp   4096
#define Bb   2048   // Ss * Nn
#define KS   32     // k-splits for Wc

typedef unsigned long long ull;

// -------- packed f32x2 helpers --------
__device__ __forceinline__ ull pk2(float lo, float hi) {
    ull r; asm("mov.b64 %0, {%1,%2};" : "=l"(r) : "f"(lo), "f"(hi)); return r;
}
__device__ __forceinline__ void upk2(ull v, float& lo, float& hi) {
    asm("mov.b64 {%0,%1}, %2;" : "=f"(lo), "=f"(hi) : "l"(v));
}
__device__ __forceinline__ ull ffma2(ull a, ull b, ull c) {
    ull d; asm("fma.rn.f32x2 %0, %1, %2, %3;" : "=l"(d) : "l"(a), "l"(b), "l"(c));
    return d;
}

// -------- device scratch (no allocations allowed) --------
__device__ float g_occ[Bb * G2];          // occupancy counts (B,64)
__device__ float g_c[Bb * Aa];            // h@W_dec + b_dec + b_enc
__device__ float g_ctx[Bb];               // attention-pooled scalar context
__device__ float g_wc[70 * Aa];           // fused weight (69 rows) + bias row (atomic acc)
__device__ float g_y[Bb * Aa];            // pre-norm activations
__device__ float g_sum[Aa];               // column sums (atomic acc)
__device__ float g_sumsq[Aa];             // column sumsq (atomic acc)

// ---------------------------------------------------------------------------
// NODE 1: c[b,a] = h@W_dec + b_dec + b_enc, PLUS zero g_occ/g_wc/g_sum/g_sumsq.
// grid (4 a-tiles, 128 b-tiles) @256 threads.
__global__ __launch_bounds__(256) void prep_kernel(const float* __restrict__ h,
                                                   const float* __restrict__ Wd,
                                                   const float* __restrict__ bd,
                                                   const float* __restrict__ be) {
    // ---- fold-in: zero scratch buffers (131072 threads cover 51200 float4) ----
    {
        int gidx = (blockIdx.y * 4 + blockIdx.x) * 256 + threadIdx.x;
        const float4 z = make_float4(0.f, 0.f, 0.f, 0.f);
        if (gidx < 32768) {
            reinterpret_cast<float4*>(g_occ)[gidx] = z;
        } else if (gidx < 32768 + 17920) {
            reinterpret_cast<float4*>(g_wc)[gidx - 32768] = z;
        } else if (gidx < 32768 + 17920 + 256) {
            reinterpret_cast<float4*>(g_sum)[gidx - 32768 - 17920] = z;
        } else if (gidx < 32768 + 17920 + 512) {
            reinterpret_cast<float4*>(g_sumsq)[gidx - 32768 - 17920 - 256] = z;
        }
    }

    int a  = blockIdx.x * 256 + threadIdx.x;
    int b0 = blockIdx.y * 16;
    __shared__ __align__(16) float hp[Hh * 16];   // hp[k*16 + bl] = h[b0+bl][k]
    for (int idx = threadIdx.x; idx < 16 * Hh; idx += 256) {
        int bl = idx >> 6, k = idx & 63;
        hp[k * 16 + bl] = h[(b0 + bl) * Hh + k];
    }
    __syncthreads();

    ull acc[8] = {0, 0, 0, 0, 0, 0, 0, 0};
    const ulonglong2* hpu = reinterpret_cast<const ulonglong2*>(hp);
#pragma unroll 8
    for (int k = 0; k < Hh; k++) {
        float w = Wd[k * Aa + a];
        ull ww = pk2(w, w);
#pragma unroll
        for (int jj = 0; jj < 4; jj++) {
            ulonglong2 v = hpu[k * 4 + jj];
            acc[2 * jj]     = ffma2(v.x, ww, acc[2 * jj]);
            acc[2 * jj + 1] = ffma2(v.y, ww, acc[2 * jj + 1]);
        }
    }
    float bias = bd[a] + be[a];
#pragma unroll
    for (int j = 0; j < 8; j++) {
        float lo, hi; upk2(acc[j], lo, hi);
        g_c[(size_t)(b0 + 2 * j) * Aa + a]     = lo + bias;
        g_c[(size_t)(b0 + 2 * j + 1) * Aa + a] = hi + bias;
    }
}

// ---------------------------------------------------------------------------
// NODE 2: fat kernel — blocks [0,256): occupancy binning (8 peds/block);
//         blocks [256,768): Wc = [W_out;b_out]@W_mlp, atomically into g_wc.
__global__ __launch_bounds__(256) void occwc_kernel(const float* __restrict__ end_pos,
                                                    const float* __restrict__ scene,
                                                    const float* __restrict__ Wo,
                                                    const float* __restrict__ bo,
                                                    const float* __restrict__ Wm) {
    if (blockIdx.x < 256) {
        // ---------------- occupancy part ----------------
        int grp = blockIdx.x & 7;
        int s   = blockIdx.x >> 3;
        int pedbase = s * 64 + grp * 8;

        __shared__ int bins[8][G2];
        __shared__ float4 boxsh[8];
        for (int i = threadIdx.x; i < 8 * G2; i += 256) ((int*)bins)[i] = 0;
        if (threadIdx.x < 8) {
            float ex = end_pos[(pedbase + threadIdx.x) * 2 + 0];
            float ey = end_pos[(pedbase + threadIdx.x) * 2 + 1];
            boxsh[threadIdx.x] = make_float4(ex - 1.0f, ey + 1.0f, ex + 1.0f, ey - 1.0f);
        }
        __syncthreads();

        float4 bx[8];
#pragma unroll
        for (int j = 0; j < 8; j++) bx[j] = boxsh[j];

        const float2* sc = reinterpret_cast<const float2*>(scene) + (size_t)s * Pp;
        for (int p = threadIdx.x; p < Pp; p += 256) {
            float2 q = sc[p];
#pragma unroll
            for (int j = 0; j < 8; j++) {
                bool in = (q.x < bx[j].z) && (q.x > bx[j].x) &&
                          (q.y < bx[j].y) && (q.y > bx[j].w);
                if (in) {
                    float cx = floorf(((q.x - bx[j].x) / 2.0f) * 8.0f);
                    float cy = floorf(((bx[j].y - q.y) / 2.0f) * 8.0f);
                    int cell = (int)(cx + cy * 8.0f);
                    if (cell >= 0 && cell < G2) {
                        atomicAdd(&bins[j][cell], 1);
                    } else {
                        long flat = (long)(pedbase + j) * G2 + cell;
                        if (flat >= 0 && flat < (long)Bb * G2)
                            atomicAdd(&g_occ[flat], 1.0f);   // rare bleed, exact int adds
                    }
                }
            }
        }
        __syncthreads();
        for (int i = threadIdx.x; i < 8 * G2; i += 256) {
            int v = ((int*)bins)[i];
            if (v) atomicAdd(&g_occ[pedbase * G2 + i], (float)v);
        }
    } else {
        // ---------------- Wc part ----------------
        int wcb = blockIdx.x - 256;          // 0..511
        int a   = (wcb & 3) * 256 + threadIdx.x;
        int r0  = ((wcb >> 2) & 3) * 18;
        int k0  = (wcb >> 4) * 32;
        __shared__ __align__(16) float ws[9 * 32 * 2];   // pair-interleaved

        for (int idx = threadIdx.x; idx < 9 * 32; idx += 256) {
            int p = idx >> 5, k = idx & 31;
            int r = r0 + 2 * p;
            float v0 = 0.f, v1 = 0.f;
            if (r < 69)       v0 = Wo[r * Aa + k0 + k];
            else if (r == 69) v0 = bo[k0 + k];
            if (r + 1 < 69)       v1 = Wo[(r + 1) * Aa + k0 + k];
            else if (r + 1 == 69) v1 = bo[k0 + k];
            ws[idx * 2]     = v0;
            ws[idx * 2 + 1] = v1;
        }
        __syncthreads();

        ull acc[9];
#pragma unroll
        for (int p = 0; p < 9; p++) acc[p] = 0ull;

        const ulonglong2* wsu = reinterpret_cast<const ulonglong2*>(ws);
#pragma unroll 2
        for (int k = 0; k < 32; k += 2) {
            float w0 = Wm[(size_t)(k0 + k) * Aa + a];
            float w1 = Wm[(size_t)(k0 + k + 1) * Aa + a];
            ull ww0 = pk2(w0, w0), ww1 = pk2(w1, w1);
#pragma unroll
            for (int p = 0; p < 9; p++) {
                ulonglong2 v = wsu[p * 16 + (k >> 1)];
                acc[p] = ffma2(v.x, ww0, acc[p]);
                acc[p] = ffma2(v.y, ww1, acc[p]);
            }
        }
#pragma unroll
        for (int p = 0; p < 9; p++) {
            int r = r0 + 2 * p;
            float lo, hi; upk2(acc[p], lo, hi);
            if (r < 70)     atomicAdd(&g_wc[r * Aa + a], lo);
            if (r + 1 < 70) atomicAdd(&g_wc[(r + 1) * Aa + a], hi);
        }
    }
}

// ---------------------------------------------------------------------------
// NODE 3: fused e / softmax / ctx, packed over the a-dimension.
//    block 128 = 8 b-rows x 16 threads, 4 g per thread. grid: B/8 = 256.
__global__ __launch_bounds__(128) void ectx_kernel(const float* __restrict__ We,
                                                   const float* __restrict__ wf) {
    int b0  = blockIdx.x * 8;
    int tid = threadIdx.x;
    int bl  = tid >> 4;   // 0..7 local b
    int gq  = tid & 15;
    int b   = b0 + bl;

    __shared__ __align__(16) float we_s[128], wf_s[128];
    __shared__ __align__(16) float c_s[8][132];   // 132: conflict-free, 528B rows

    float og[4];
    ull ogw[4], e2[4];
#pragma unroll
    for (int i = 0; i < 4; i++) {
        og[i]  = g_occ[b * G2 + gq * 4 + i];
        ogw[i] = pk2(og[i], og[i]);
        e2[i]  = 0ull;
    }

    for (int a0 = 0; a0 < Aa; a0 += 128) {
        __syncthreads();
        we_s[tid] = We[a0 + tid];
        wf_s[tid] = wf[a0 + tid];
        for (int i = tid; i < 8 * 128; i += 128) {
            int bi = i >> 7, j = i & 127;
            c_s[bi][j] = g_c[(size_t)(b0 + bi) * Aa + a0 + j];
        }
        __syncthreads();
        const ull* weu = reinterpret_cast<const ull*>(we_s);
        const ull* wfu = reinterpret_cast<const ull*>(wf_s);
        const ull* cu  = reinterpret_cast<const ull*>(&c_s[bl][0]);
#pragma unroll 4
        for (int jj = 0; jj < 64; jj++) {
            ull we2 = weu[jj];
            ull wf2 = wfu[jj];
            ull c2  = cu[jj];
#pragma unroll
            for (int i = 0; i < 4; i++) {
                ull x2 = ffma2(ogw[i], we2, c2);
                float lo, hi; upk2(x2, lo, hi);
                lo = fmaxf(lo, 0.0f);
                hi = fmaxf(hi, 0.0f);
                e2[i] = ffma2(pk2(lo, hi), wf2, e2[i]);
            }
        }
    }

    float e[4];
#pragma unroll
    for (int i = 0; i < 4; i++) { float lo, hi; upk2(e2[i], lo, hi); e[i] = lo + hi; }

    float m = fmaxf(fmaxf(e[0], e[1]), fmaxf(e[2], e[3]));
#pragma unroll
    for (int off = 8; off >= 1; off >>= 1)
        m = fmaxf(m, __shfl_xor_sync(0xffffffffu, m, off, 16));
    float s = 0.f, cx = 0.f;
#pragma unroll
    for (int i = 0; i < 4; i++) {
        float ex = __expf(e[i] - m);
        s += ex;
        cx = fmaf(ex, og[i], cx);
    }
#pragma unroll
    for (int off = 8; off >= 1; off >>= 1) {
        s  += __shfl_xor_sync(0xffffffffu, s, off, 16);
        cx += __shfl_xor_sync(0xffffffffu, cx, off, 16);
    }
    if (gq == 0) g_ctx[b] = cx / s;
}

// ---------------------------------------------------------------------------
// NODE 4: y[b,a] = u@Wc + bias; atomically accumulates column sum/sumsq.
__global__ __launch_bounds__(128) void y_kernel(const float* __restrict__ h,
                                                const float* __restrict__ ep,
                                                const float* __restrict__ rp,
                                                const float* __restrict__ bm) {
    int a  = blockIdx.x * 128 + threadIdx.x;
    int b0 = blockIdx.y * 16;
    __shared__ __align__(16) float us[69 * 16];   // us[r*16 + bl] = u[b0+bl][r]
    for (int idx = threadIdx.x; idx < 69 * 16; idx += 128) {
        int r = idx >> 4, bl = idx & 15;
        int b = b0 + bl;
        float v;
        if (r == 0)      v = g_ctx[b];
        else if (r < 65) v = h[b * Hh + (r - 1)];
        else if (r < 67) v = ep[b * 2 + (r - 65)];
        else             v = rp[b * 2 + (r - 67)];
        us[idx] = v;
    }
    __syncthreads();

    ull acc[8] = {0, 0, 0, 0, 0, 0, 0, 0};
    const ulonglong2* usu = reinterpret_cast<const ulonglong2*>(us);
#pragma unroll 4
    for (int r = 0; r < 69; r++) {
        float w = g_wc[r * Aa + a];
        ull ww = pk2(w, w);
#pragma unroll
        for (int jj = 0; jj < 4; jj++) {
            ulonglong2 v = usu[r * 4 + jj];
            acc[2 * jj]     = ffma2(v.x, ww, acc[2 * jj]);
            acc[2 * jj + 1] = ffma2(v.y, ww, acc[2 * jj + 1]);
        }
    }
    float bias = g_wc[69 * Aa + a] + bm[a];
    float s = 0.f, s2 = 0.f;
#pragma unroll
    for (int j = 0; j < 8; j++) {
        float lo, hi; upk2(acc[j], lo, hi);
        float v0 = lo + bias, v1 = hi + bias;
        g_y[(size_t)(b0 + 2 * j) * Aa + a]     = v0;
        g_y[(size_t)(b0 + 2 * j + 1) * Aa + a] = v1;
        s += v0 + v1;
        s2 = fmaf(v0, v0, s2);
        s2 = fmaf(v1, v1, s2);
    }
    atomicAdd(&g_sum[a], s);
    atomicAdd(&g_sumsq[a], s2);
}

// ---------------------------------------------------------------------------
// NODE 5: out = relu(y * gamma*rstd + (beta - mu*gamma*rstd)), stats inline.
__global__ __launch_bounds__(256) void finalize_kernel(const float* __restrict__ gamma,
                                                       const float* __restrict__ beta,
                                                       float* __restrict__ out) {
    int idx = blockIdx.x * blockDim.x + threadIdx.x;   // over B*A/4
    const int n = Bb * Aa / 4;
    if (idx >= n) return;
    int a = (idx * 4) & (Aa - 1);
    float4 v  = reinterpret_cast<const float4*>(g_y)[idx];
    float4 s4 = *reinterpret_cast<const float4*>(&g_sum[a]);
    float4 q4 = *reinterpret_cast<const float4*>(&g_sumsq[a]);
    float4 gm = *reinterpret_cast<const float4*>(&gamma[a]);
    float4 bt = *reinterpret_cast<const float4*>(&beta[a]);
    const float inv = 1.0f / (float)Bb;
    float4 o;
    {
        float mu = s4.x * inv, var = q4.x * inv - mu * mu;
        float sc = gm.x * rsqrtf(var + 1e-5f);
        o.x = fmaxf(fmaf(v.x, sc, bt.x - mu * sc), 0.f);
    }
    {
        float mu = s4.y * inv, var = q4.y * inv - mu * mu;
        float sc = gm.y * rsqrtf(var + 1e-5f);
        o.y = fmaxf(fmaf(v.y, sc, bt.y - mu * sc), 0.f);
    }
    {
        float mu = s4.z * inv, var = q4.z * inv - mu * mu;
        float sc = gm.z * rsqrtf(var + 1e-5f);
        o.z = fmaxf(fmaf(v.z, sc, bt.z - mu * sc), 0.f);
    }
    {
        float mu = s4.w * inv, var = q4.w * inv - mu * mu;
        float sc = gm.w * rsqrtf(var + 1e-5f);
        o.w = fmaxf(fmaf(v.w, sc, bt.w - mu * sc), 0.f);
    }
    reinterpret_cast<float4*>(out)[idx] = o;
}

// ---------------------------------------------------------------------------
extern "C" void kernel_launch(void* const* d_in, const int* in_sizes, int n_in,
                              void* d_out, int out_size) {
    const float* h_states = (const float*)d_in[0];   // (1,B,H)
    const float* end_pos  = (const float*)d_in[1];   // (B,2)
    const float* rel_pos  = (const float*)d_in[2];   // (B,2)
    const float* scene    = (const float*)d_in[3];   // (S,P,2)
    const float* W_enc    = (const float*)d_in[4];   // (1,A)
    const float* b_enc    = (const float*)d_in[5];   // (A)
    const float* W_dec    = (const float*)d_in[6];   // (H,A)
    const float* b_dec    = (const float*)d_in[7];   // (A)
    const float* w_full   = (const float*)d_in[8];   // (A,1)
    // d_in[9]  = b_full (softmax-shift invariant -> unused)
    const float* W_out    = (const float*)d_in[10];  // (69,A)
    const float* b_out    = (const float*)d_in[11];  // (A)
    const float* W_mlp    = (const float*)d_in[12];  // (A,A)
    const float* b_mlp    = (const float*)d_in[13];  // (A)
    const float* gamma    = (const float*)d_in[14];  // (A)
    const float* beta     = (const float*)d_in[15];  // (A)
    float* out = (float*)d_out;

    // 5-node graph; each node depends on the previous (single stream).
    prep_kernel<<<dim3(4, 128), 256>>>(h_states, W_dec, b_dec, b_enc);
    occwc_kernel<<<256 + 512, 256>>>(end_pos, scene, W_out, b_out, W_mlp);
    ectx_kernel<<<Bb / 8, 128>>>(W_enc, w_full);
    y_kernel<<<dim3(Aa / 128, Bb / 16), 128>>>(h_states, end_pos, rel_pos, b_mlp);
    finalize_kernel<<<(Bb * Aa / 4 + 255) / 256, 256>>>(gamma, beta, out);
}